// round 1
// baseline (speedup 1.0000x reference)
#include <cuda_runtime.h>
#include <cstdint>

// Problem constants (fixed by the dataset: IN_SHAPE=(32,3,512,512), OUT=256)
#define BC      96           // 32*3 planes
#define IN_HW   512
#define OUT_HW  256
#define MAX_TAPS 32

// Scratch for the intermediate (B,C,H=512,Wout=256) tensor: 96*512*256 floats = 48 MiB.
__device__ float g_scratch[(size_t)BC * IN_HW * OUT_HW];

// ---------------------------------------------------------------------------
// Pass 1: resize the innermost (W) axis. One block per input row.
// Row (512 floats) is staged in shared memory; each of 256 threads computes
// one output column with `taps` gathered multiply-adds.
// ---------------------------------------------------------------------------
__global__ __launch_bounds__(256) void resize_w_kernel(
    const float* __restrict__ in,     // (BC*IN_HW, IN_HW)
    const float* __restrict__ w,      // (taps, OUT_HW)
    const int*   __restrict__ fov,    // (taps, OUT_HW)
    float*       __restrict__ out,    // (BC*IN_HW, OUT_HW)
    int taps)
{
    __shared__ float row[IN_HW];

    const int r = blockIdx.x;                      // which input row (0..BC*IN_HW-1)
    const float2* src = reinterpret_cast<const float2*>(in + (size_t)r * IN_HW);
    reinterpret_cast<float2*>(row)[threadIdx.x] = src[threadIdx.x];
    __syncthreads();

    const int ow = threadIdx.x;                    // 0..255
    float acc = 0.0f;
    #pragma unroll 4
    for (int t = 0; t < taps; ++t) {
        const int   idx = fov[t * OUT_HW + ow];    // 0..511
        const float wt  = w  [t * OUT_HW + ow];
        acc = fmaf(wt, row[idx], acc);
    }
    out[(size_t)r * OUT_HW + ow] = acc;
}

// ---------------------------------------------------------------------------
// Pass 2: resize the H axis. Block = 256 threads over ow (fully coalesced),
// grid = (OUT_HW oh, BC planes). Weights/indices are uniform per block.
// ---------------------------------------------------------------------------
__global__ __launch_bounds__(256) void resize_h_kernel(
    const float* __restrict__ tmp,    // (BC, IN_HW, OUT_HW)
    const float* __restrict__ w,      // (taps, OUT_HW)
    const int*   __restrict__ fov,    // (taps, OUT_HW)
    float*       __restrict__ out,    // (BC, OUT_HW, OUT_HW)
    int taps)
{
    __shared__ float ws[MAX_TAPS];
    __shared__ int   fs[MAX_TAPS];

    const int oh    = blockIdx.x;
    const int plane = blockIdx.y;

    if (threadIdx.x < taps) {
        ws[threadIdx.x] = w  [threadIdx.x * OUT_HW + oh];
        fs[threadIdx.x] = fov[threadIdx.x * OUT_HW + oh];
    }
    __syncthreads();

    const int ow = threadIdx.x;
    const float* base = tmp + (size_t)plane * IN_HW * OUT_HW;

    float acc = 0.0f;
    #pragma unroll 4
    for (int t = 0; t < taps; ++t) {
        acc = fmaf(ws[t], base[(size_t)fs[t] * OUT_HW + ow], acc);
    }
    out[((size_t)plane * OUT_HW + oh) * OUT_HW + ow] = acc;
}

// ---------------------------------------------------------------------------
// kernel_launch: inputs per metadata order:
//   d_in[0] = in_tensor (f32, 32*3*512*512)
//   d_in[1] = w2  (f32, taps*256)   -- H-axis weights
//   d_in[2] = fov2 (i32, taps*256)  -- H-axis indices
//   d_in[3] = w3  (f32, taps*256)   -- W-axis weights (identical table)
//   d_in[4] = fov3 (i32, taps*256)  -- W-axis indices
// ---------------------------------------------------------------------------
extern "C" void kernel_launch(void* const* d_in, const int* in_sizes, int n_in,
                              void* d_out, int out_size)
{
    const float* in   = (const float*)d_in[0];
    const float* w2   = (const float*)d_in[1];
    const int*   fov2 = (const int*)  d_in[2];
    const float* w3   = (const float*)d_in[3];
    const int*   fov3 = (const int*)  d_in[4];
    float* out = (float*)d_out;

    const int taps = in_sizes[1] / OUT_HW;   // w2 has taps*256 elements

    float* scratch;
    cudaGetSymbolAddress((void**)&scratch, g_scratch);

    // Pass 1: W axis (innermost). One block per input row.
    resize_w_kernel<<<BC * IN_HW, 256>>>(in, w3, fov3, scratch, taps);

    // Pass 2: H axis.
    dim3 grid2(OUT_HW, BC);
    resize_h_kernel<<<grid2, 256>>>(scratch, w2, fov2, out, taps);
}

// round 2
// speedup vs baseline: 1.6242x; 1.6242x over previous
#include <cuda_runtime.h>
#include <cstdint>

// Problem constants (fixed by dataset: IN=(32,3,512,512), OUT=256, scale=0.5)
#define BC      96            // 32*3 planes
#define IN_HW   512
#define OUT_HW  256
#define MAX_T   12            // taps is ~10 at scale 0.5; 12 is a safe unroll bound
#define ROWS_PER_BLK 8

// Scratch for intermediate (BC, OUT_HW oh, IN_HW w): 96*256*512 floats = 48 MiB.
__device__ float g_scratch[(size_t)BC * OUT_HW * IN_HW];

// ---------------------------------------------------------------------------
// Pass 1: resize H axis first (fully coalesced along W, float4-vectorized).
//   mid[plane][oh][w] = sum_t wh[t][oh] * in[plane][fovh[t][oh]][w]
// Block = 128 threads (each owns 4 consecutive w). Grid = (256 oh, 96 planes).
// Weights/indices are uniform per block -> smem broadcast.
// ---------------------------------------------------------------------------
__global__ __launch_bounds__(128) void resize_h_kernel(
    const float4* __restrict__ in,    // (BC, IN_HW, IN_HW/4)
    const float*  __restrict__ w,     // (taps, OUT_HW)
    const int*    __restrict__ fov,   // (taps, OUT_HW)
    float4*       __restrict__ mid,   // (BC, OUT_HW, IN_HW/4)
    int taps)
{
    __shared__ float ws[MAX_T];
    __shared__ int   fs[MAX_T];

    const int oh    = blockIdx.x;
    const int plane = blockIdx.y;
    const int tid   = threadIdx.x;    // 0..127 -> 4 floats each

    if (tid < taps) {
        ws[tid] = w  [tid * OUT_HW + oh];
        fs[tid] = fov[tid * OUT_HW + oh];
    }
    __syncthreads();

    const float4* base = in + (size_t)plane * IN_HW * (IN_HW / 4);

    float4 acc = make_float4(0.f, 0.f, 0.f, 0.f);
    #pragma unroll
    for (int t = 0; t < MAX_T; ++t) {
        if (t < taps) {
            const float  wt = ws[t];
            const float4 v  = base[(size_t)fs[t] * (IN_HW / 4) + tid];
            acc.x = fmaf(wt, v.x, acc.x);
            acc.y = fmaf(wt, v.y, acc.y);
            acc.z = fmaf(wt, v.z, acc.z);
            acc.w = fmaf(wt, v.w, acc.w);
        }
    }
    mid[((size_t)plane * OUT_HW + oh) * (IN_HW / 4) + tid] = acc;
}

// ---------------------------------------------------------------------------
// Pass 2: resize W axis on the (BC*OUT_HW, IN_HW) intermediate.
// Block = 256 threads (one per ow), processes ROWS_PER_BLK rows:
//   - per-thread weight/index tables live in REGISTERS (loaded once)
//   - 8 rows staged into smem in one coalesced burst, single __syncthreads
//   - 10 LDS gathers + 1 coalesced STG per output
// ---------------------------------------------------------------------------
__global__ __launch_bounds__(256) void resize_w_kernel(
    const float* __restrict__ mid,    // (BC*OUT_HW, IN_HW)
    const float* __restrict__ w,      // (taps, OUT_HW)
    const int*   __restrict__ fov,    // (taps, OUT_HW)
    float*       __restrict__ out,    // (BC*OUT_HW, OUT_HW)
    int taps)
{
    __shared__ float rows[ROWS_PER_BLK][IN_HW];

    const int ow = threadIdx.x;       // 0..255

    // Per-thread tables -> registers (fully unrolled so arrays stay in regs).
    float wr[MAX_T];
    int   ir[MAX_T];
    #pragma unroll
    for (int t = 0; t < MAX_T; ++t) {
        if (t < taps) {
            wr[t] = w  [t * OUT_HW + ow];
            ir[t] = fov[t * OUT_HW + ow];
        } else {
            wr[t] = 0.f;
            ir[t] = 0;
        }
    }

    // Stage ROWS_PER_BLK rows (8 * 512 floats) coalesced as float2.
    const size_t row0 = (size_t)blockIdx.x * ROWS_PER_BLK;
    const float2* src = reinterpret_cast<const float2*>(mid + row0 * IN_HW);
    float2* dst = reinterpret_cast<float2*>(&rows[0][0]);
    #pragma unroll
    for (int i = 0; i < ROWS_PER_BLK * (IN_HW / 2) / 256; ++i) {
        dst[i * 256 + ow] = src[i * 256 + ow];
    }
    __syncthreads();

    // Compute 8 outputs per thread.
    float* obase = out + row0 * OUT_HW + ow;
    #pragma unroll
    for (int r = 0; r < ROWS_PER_BLK; ++r) {
        float acc = 0.f;
        #pragma unroll
        for (int t = 0; t < MAX_T; ++t) {
            if (t < taps) acc = fmaf(wr[t], rows[r][ir[t]], acc);
        }
        obase[r * OUT_HW] = acc;
    }
}

// ---------------------------------------------------------------------------
// Inputs (metadata order):
//   d_in[0] = in_tensor (f32, 96*512*512)
//   d_in[1] = w2  (f32, taps*256)   d_in[2] = fov2 (i32, taps*256)   -- H axis
//   d_in[3] = w3  (f32, taps*256)   d_in[4] = fov3 (i32, taps*256)   -- W axis
// ---------------------------------------------------------------------------
extern "C" void kernel_launch(void* const* d_in, const int* in_sizes, int n_in,
                              void* d_out, int out_size)
{
    const float* in   = (const float*)d_in[0];
    const float* w2   = (const float*)d_in[1];
    const int*   fov2 = (const int*)  d_in[2];
    const float* w3   = (const float*)d_in[3];
    const int*   fov3 = (const int*)  d_in[4];
    float* out = (float*)d_out;

    const int taps = in_sizes[1] / OUT_HW;

    float* scratch;
    cudaGetSymbolAddress((void**)&scratch, g_scratch);

    // Pass 1: H axis (coalesced, vectorized).
    dim3 grid1(OUT_HW, BC);
    resize_h_kernel<<<grid1, 128>>>((const float4*)in, w2, fov2,
                                    (float4*)scratch, taps);

    // Pass 2: W axis (register tables + smem row gather).
    const int nrows = BC * OUT_HW;                    // 24576 rows
    resize_w_kernel<<<nrows / ROWS_PER_BLK, 256>>>(scratch, w3, fov3, out, taps);
}